// round 1
// baseline (speedup 1.0000x reference)
#include <cuda_runtime.h>

#define N_NODES 100000
#define N_EDGES 1600000
#define F 64

typedef unsigned long long ull;

// ---------------- scratch (static device globals; no allocation) ----------------
__device__ int   g_deg[N_NODES];
__device__ int   g_cursor[N_NODES];
__device__ int   g_row_ptr[N_NODES + 1];
__device__ int   g_csr_src[N_EDGES];
__device__ float g_mean[(size_t)N_NODES * F];
__device__ float g_h1[(size_t)N_NODES * F];
__device__ float g_h2[(size_t)N_NODES * F];
__device__ float g_sa[N_NODES];
__device__ float g_sb[N_NODES];

// ---------------- packed f32x2 helpers (Blackwell FFMA2) ----------------
__device__ __forceinline__ ull fma2(ull a, ull b, ull c) {
    ull d;
    asm("fma.rn.f32x2 %0, %1, %2, %3;" : "=l"(d) : "l"(a), "l"(b), "l"(c));
    return d;
}
__device__ __forceinline__ ull pack2(float x, float y) {
    ull r; asm("mov.b64 %0, {%1, %2};" : "=l"(r) : "f"(x), "f"(y)); return r;
}
__device__ __forceinline__ float hsum2(ull a) {
    float x, y; asm("mov.b64 {%0, %1}, %2;" : "=f"(x), "=f"(y) : "l"(a)); return x + y;
}

// ---------------- CSR build ----------------
__global__ void zero_kernel() {
    int i = blockIdx.x * blockDim.x + threadIdx.x;
    if (i < N_NODES) g_deg[i] = 0;
}

__global__ void hist_kernel(const int* __restrict__ ei) {
    int e = blockIdx.x * blockDim.x + threadIdx.x;
    if (e < N_EDGES) atomicAdd(&g_deg[ei[N_EDGES + e]], 1);
}

// single-block exclusive scan of degrees -> row_ptr (also seeds cursor)
__global__ void scan_kernel() {
    __shared__ int sums[1024];
    const int t = threadIdx.x;
    const int CH = (N_NODES + 1023) / 1024;   // 98
    int begin = t * CH;
    int end = begin + CH; if (end > N_NODES) end = N_NODES;
    int s = 0;
    for (int i = begin; i < end; i++) s += g_deg[i];
    sums[t] = s;
    __syncthreads();
    for (int off = 1; off < 1024; off <<= 1) {
        int v = (t >= off) ? sums[t - off] : 0;
        __syncthreads();
        sums[t] += v;
        __syncthreads();
    }
    int run = (t == 0) ? 0 : sums[t - 1];
    for (int i = begin; i < end; i++) {
        g_row_ptr[i] = run;
        g_cursor[i]  = run;
        run += g_deg[i];
    }
    if (t == 1023) g_row_ptr[N_NODES] = sums[1023];
}

__global__ void fill_kernel(const int* __restrict__ ei) {
    int e = blockIdx.x * blockDim.x + threadIdx.x;
    if (e >= N_EDGES) return;
    int src = ei[e];
    int dst = ei[N_EDGES + e];
    int pos = atomicAdd(&g_cursor[dst], 1);
    g_csr_src[pos] = src;
}

// ---------------- mean aggregation (CSR pull, 16 threads/node, float4 lanes) ----------------
__global__ void agg_kernel(const float* __restrict__ x0, int layer) {
    const float* __restrict__ xin = (layer == 0) ? x0 : (const float*)g_h1;
    int gid  = blockIdx.x * blockDim.x + threadIdx.x;
    int node = gid >> 4;
    int lane = gid & 15;
    if (node >= N_NODES) return;

    const unsigned hm = ((threadIdx.x & 31) < 16) ? 0x0000FFFFu : 0xFFFF0000u;

    int beg = g_row_ptr[node];
    int end = g_row_ptr[node + 1];
    float4 acc = make_float4(0.f, 0.f, 0.f, 0.f);

    for (int base = beg; base < end; base += 16) {
        int my  = base + lane;
        int idx = (my < end) ? g_csr_src[my] : 0;
        int cnt = end - base; if (cnt > 16) cnt = 16;
        for (int t = 0; t < cnt; t++) {
            int s = __shfl_sync(hm, idx, t, 16);
            float4 v = __ldg((const float4*)xin + s * 16 + lane);
            acc.x += v.x; acc.y += v.y; acc.z += v.z; acc.w += v.w;
        }
    }
    float inv = (end > beg) ? 1.0f / (float)(end - beg) : 0.0f;
    acc.x *= inv; acc.y *= inv; acc.z *= inv; acc.w *= inv;
    ((float4*)g_mean)[node * 16 + lane] = acc;
}

// ---------------- SAGE transform: h = relu(mean @ Wl^T + b + x @ Wr^T) ----------------
// weights register-resident, one output feature per thread, f32x2 packed FMA.
__global__ void __launch_bounds__(256, 1) transform_kernel(
    const float* __restrict__ x0,
    const float* __restrict__ Wl, const float* __restrict__ bl,
    const float* __restrict__ Wr, int layer)
{
    const float* __restrict__ xin = (layer == 0) ? x0 : (const float*)g_h1;
    float* hout = (layer == 0) ? g_h1 : g_h2;

    const int j = threadIdx.x & 63;   // output feature
    const int g = threadIdx.x >> 6;   // node-group within block (0..3)

    ull wl[32], wr[32];
#pragma unroll
    for (int k = 0; k < 16; k++) {
        float4 a = __ldg((const float4*)Wl + j * 16 + k);
        float4 b = __ldg((const float4*)Wr + j * 16 + k);
        wl[2 * k]     = pack2(a.x, a.y);
        wl[2 * k + 1] = pack2(a.z, a.w);
        wr[2 * k]     = pack2(b.x, b.y);
        wr[2 * k + 1] = pack2(b.z, b.w);
    }
    const float bias = __ldg(bl + j);

    for (int n = blockIdx.x * 4 + g; n < N_NODES; n += gridDim.x * 4) {
        const float4* m4 = (const float4*)g_mean + n * 16;
        const float4* x4 = (const float4*)xin + n * 16;
        ull a0 = 0ULL, a1 = 0ULL, a2 = 0ULL, a3 = 0ULL;
#pragma unroll
        for (int k = 0; k < 16; k++) {
            float4 mv = __ldg(m4 + k);
            float4 xv = __ldg(x4 + k);
            a0 = fma2(wl[2 * k],     pack2(mv.x, mv.y), a0);
            a1 = fma2(wl[2 * k + 1], pack2(mv.z, mv.w), a1);
            a2 = fma2(wr[2 * k],     pack2(xv.x, xv.y), a2);
            a3 = fma2(wr[2 * k + 1], pack2(xv.z, xv.w), a3);
        }
        float s = hsum2(a0) + hsum2(a1) + hsum2(a2) + hsum2(a3) + bias;
        hout[(size_t)n * 64 + j] = fmaxf(s, 0.0f);
    }
}

// ---------------- per-node edge-score halves: sa = h2·Wlin[:64], sb = h2·Wlin[64:] ----------------
__global__ void sab_kernel(const float* __restrict__ Wlin) {
    int n = blockIdx.x * blockDim.x + threadIdx.x;
    if (n >= N_NODES) return;
    const float4* h4 = (const float4*)g_h2 + n * 16;
    float sa = 0.f, sb = 0.f;
#pragma unroll
    for (int k = 0; k < 16; k++) {
        float4 h  = __ldg(h4 + k);
        float4 wa = __ldg((const float4*)Wlin + k);
        float4 wb = __ldg((const float4*)Wlin + 16 + k);
        sa += h.x * wa.x + h.y * wa.y + h.z * wa.z + h.w * wa.w;
        sb += h.x * wb.x + h.y * wb.y + h.z * wb.z + h.w * wb.w;
    }
    g_sa[n] = sa;
    g_sb[n] = sb;
}

// ---------------- final edge scores ----------------
__global__ void edge_kernel(const int* __restrict__ ei,
                            const float* __restrict__ blin,
                            float* __restrict__ out)
{
    int e = blockIdx.x * blockDim.x + threadIdx.x;
    if (e >= N_EDGES) return;
    int s = ei[e];
    int d = ei[N_EDGES + e];
    out[e] = g_sa[s] + g_sb[d] + __ldg(blin);
}

// ---------------- launch ----------------
extern "C" void kernel_launch(void* const* d_in, const int* in_sizes, int n_in,
                              void* d_out, int out_size)
{
    const float* x    = (const float*)d_in[0];
    const int*   ei   = (const int*)  d_in[1];
    const float* W1l  = (const float*)d_in[2];
    const float* b1l  = (const float*)d_in[3];
    const float* W1r  = (const float*)d_in[4];
    const float* W2l  = (const float*)d_in[5];
    const float* b2l  = (const float*)d_in[6];
    const float* W2r  = (const float*)d_in[7];
    const float* Wlin = (const float*)d_in[8];
    const float* blin = (const float*)d_in[9];
    float* out = (float*)d_out;

    const int EB = (N_EDGES + 255) / 256;

    zero_kernel<<<(N_NODES + 255) / 256, 256>>>();
    hist_kernel<<<EB, 256>>>(ei);
    scan_kernel<<<1, 1024>>>();
    fill_kernel<<<EB, 256>>>(ei);

    // layer 1
    agg_kernel<<<(N_NODES * 16 + 255) / 256, 256>>>(x, 0);
    transform_kernel<<<152, 256>>>(x, W1l, b1l, W1r, 0);

    // layer 2
    agg_kernel<<<(N_NODES * 16 + 255) / 256, 256>>>(x, 1);
    transform_kernel<<<152, 256>>>(x, W2l, b2l, W2r, 1);

    // edge scoring
    sab_kernel<<<(N_NODES + 255) / 256, 256>>>(Wlin);
    edge_kernel<<<EB, 256>>>(ei, blin, out);
}